// round 12
// baseline (speedup 1.0000x reference)
#include <cuda_runtime.h>
#include <cstdint>

// IF neuron multi-step scan, hard reset:
//   h_t = x_t + v_{t-1};  s_t = (h_t >= 1) ? 1 : 0;  v_t = s_t ? 0 : h_t
//
// R12 (final form): R10/R11 structure — block=128, one float4 lane/thread,
// batch-4 double-buffered prefetch (8 LDG.128 in flight) — which sits at the
// measured LTS ceiling: 268MB compulsory L2 traffic / ~7.2TB/s LTS cap
// ≈ 37us. All scheduling variants converge here; bytes are irreducible.
// Residual tuning: store policy evict_last fraction 0.8 (pins ~107MB of the
// 134MB output in the 126MB L2, stably under capacity) with explicit
// evict_first secondary so the unpinned residue can't disturb the pinned
// set; loads evict_first (zero reuse).

__device__ __forceinline__ uint64_t policy_st()
{
    uint64_t p;
    asm("createpolicy.fractional.L2::evict_last.L2::evict_first.b64 %0, 0.8;"
        : "=l"(p));
    return p;
}

__device__ __forceinline__ uint64_t policy_ld()
{
    uint64_t p;
    asm("createpolicy.fractional.L2::evict_first.b64 %0, 1.0;" : "=l"(p));
    return p;
}

__device__ __forceinline__ float4 ldg_h(const float4* p, uint64_t pol)
{
    float4 r;
    asm("ld.global.nc.L2::cache_hint.v4.f32 {%0,%1,%2,%3}, [%4], %5;"
        : "=f"(r.x), "=f"(r.y), "=f"(r.z), "=f"(r.w)
        : "l"(p), "l"(pol));
    return r;
}

__device__ __forceinline__ void stg_h(float4* p, float4 v, uint64_t pol)
{
    asm volatile("st.global.L2::cache_hint.v4.f32 [%0], {%1,%2,%3,%4}, %5;"
                 :: "l"(p), "f"(v.x), "f"(v.y), "f"(v.z), "f"(v.w), "l"(pol)
                 : "memory");
}

__device__ __forceinline__ float4 if_step(float4 xv, float4& v)
{
    float h0 = xv.x + v.x;
    float h1 = xv.y + v.y;
    float h2 = xv.z + v.z;
    float h3 = xv.w + v.w;

    float4 s;
    s.x = (h0 >= 1.0f) ? 1.0f : 0.0f;
    s.y = (h1 >= 1.0f) ? 1.0f : 0.0f;
    s.z = (h2 >= 1.0f) ? 1.0f : 0.0f;
    s.w = (h3 >= 1.0f) ? 1.0f : 0.0f;

    v.x = (h0 >= 1.0f) ? 0.0f : h0;
    v.y = (h1 >= 1.0f) ? 0.0f : h1;
    v.z = (h2 >= 1.0f) ? 0.0f : h2;
    v.w = (h3 >= 1.0f) ? 0.0f : h3;
    return s;
}

#define BLOCK 128

// T must be a multiple of 4 (T=32 here).
__global__ __launch_bounds__(BLOCK, 10) void if_scan_final(
    const float4* __restrict__ x,   // [T, n4]
    const float4* __restrict__ v0,  // [n4]
    float4* __restrict__ out,       // [T, n4]
    int n4, int T)
{
    int i = blockIdx.x * BLOCK + threadIdx.x;
    if (i >= n4) return;

    uint64_t pl = policy_ld();
    uint64_t ps = policy_st();

    float4 v = v0[i];
    const float4* xp = x + i;
    float4* op = out + i;

    long long stride = n4;

    // prologue: load batch 0
    float4 buf[4];
    #pragma unroll
    for (int k = 0; k < 4; ++k)
        buf[k] = ldg_h(xp + (long long)k * stride, pl);
    xp += 4 * stride;

    for (int t = 4; t < T; t += 4) {
        // prefetch next batch (8 loads in flight per thread)
        float4 nxt[4];
        #pragma unroll
        for (int k = 0; k < 4; ++k)
            nxt[k] = ldg_h(xp + (long long)k * stride, pl);
        xp += 4 * stride;

        // compute + store current batch (write burst)
        #pragma unroll
        for (int k = 0; k < 4; ++k) {
            float4 s = if_step(buf[k], v);
            stg_h(op, s, ps);
            op += stride;
        }

        #pragma unroll
        for (int k = 0; k < 4; ++k) buf[k] = nxt[k];
    }

    // epilogue
    #pragma unroll
    for (int k = 0; k < 4; ++k) {
        float4 s = if_step(buf[k], v);
        stg_h(op, s, ps);
        op += stride;
    }
}

// Generic fallback for T not divisible by 4 (not hit for this shape).
__global__ __launch_bounds__(BLOCK) void if_scan_plain(
    const float4* __restrict__ x,
    const float4* __restrict__ v0,
    float4* __restrict__ out,
    int n4, int T)
{
    int i = blockIdx.x * BLOCK + threadIdx.x;
    if (i >= n4) return;

    float4 v = v0[i];
    const float4* xp = x + i;
    float4* op = out + i;

    for (int t = 0; t < T; ++t) {
        float4 xv = __ldcs(xp); xp += n4;
        float4 s = if_step(xv, v);
        __stcs(op, s); op += n4;
    }
}

extern "C" void kernel_launch(void* const* d_in, const int* in_sizes, int n_in,
                              void* d_out, int out_size)
{
    const float* x_seq  = (const float*)d_in[0];   // [T, B, D]
    const float* v_init = (const float*)d_in[1];   // [B, D]

    int N = in_sizes[1];              // B * D
    int T = in_sizes[0] / N;          // timesteps
    int n4 = N / 4;

    int grid = (n4 + BLOCK - 1) / BLOCK;

    if ((T & 3) == 0) {
        if_scan_final<<<grid, BLOCK>>>(
            (const float4*)x_seq, (const float4*)v_init,
            (float4*)d_out, n4, T);
    } else {
        if_scan_plain<<<grid, BLOCK>>>(
            (const float4*)x_seq, (const float4*)v_init,
            (float4*)d_out, n4, T);
    }
}

// round 13
// speedup vs baseline: 1.0088x; 1.0088x over previous
#include <cuda_runtime.h>
#include <cstdint>

// IF neuron multi-step scan, hard reset:
//   h_t = x_t + v_{t-1};  s_t = (h_t >= 1) ? 1 : 0;  v_t = s_t ? 0 : h_t
//
// FINAL (R13 = R12, confirmed at the hardware floor):
//   - block=128, one float4 lane per thread, batch-4 double-buffered
//     prefetch (8 LDG.128 in flight per thread)
//   - loads:  L2::evict_first (zero-reuse stream)
//   - stores: fractional L2::evict_last 0.8 / evict_first secondary
//     (pins ~107MB of the 134MB output in the 126MB L2)
// Floor analysis: 268MB compulsory L2 traffic / ~7.2TB/s LTS cap ≈ 37us.
// Measured 36.9us kernel = 7.26TB/s through LTS — at the cap. All scheduling
// variants (MLP 4-8, occ 40-77%, 128/256-bit, cp.async) converged to 37-44us
// with this as the minimum; bytes are irreducible (no reuse, fp32 output).

__device__ __forceinline__ uint64_t policy_st()
{
    uint64_t p;
    asm("createpolicy.fractional.L2::evict_last.L2::evict_first.b64 %0, 0.8;"
        : "=l"(p));
    return p;
}

__device__ __forceinline__ uint64_t policy_ld()
{
    uint64_t p;
    asm("createpolicy.fractional.L2::evict_first.b64 %0, 1.0;" : "=l"(p));
    return p;
}

__device__ __forceinline__ float4 ldg_h(const float4* p, uint64_t pol)
{
    float4 r;
    asm("ld.global.nc.L2::cache_hint.v4.f32 {%0,%1,%2,%3}, [%4], %5;"
        : "=f"(r.x), "=f"(r.y), "=f"(r.z), "=f"(r.w)
        : "l"(p), "l"(pol));
    return r;
}

__device__ __forceinline__ void stg_h(float4* p, float4 v, uint64_t pol)
{
    asm volatile("st.global.L2::cache_hint.v4.f32 [%0], {%1,%2,%3,%4}, %5;"
                 :: "l"(p), "f"(v.x), "f"(v.y), "f"(v.z), "f"(v.w), "l"(pol)
                 : "memory");
}

__device__ __forceinline__ float4 if_step(float4 xv, float4& v)
{
    float h0 = xv.x + v.x;
    float h1 = xv.y + v.y;
    float h2 = xv.z + v.z;
    float h3 = xv.w + v.w;

    float4 s;
    s.x = (h0 >= 1.0f) ? 1.0f : 0.0f;
    s.y = (h1 >= 1.0f) ? 1.0f : 0.0f;
    s.z = (h2 >= 1.0f) ? 1.0f : 0.0f;
    s.w = (h3 >= 1.0f) ? 1.0f : 0.0f;

    v.x = (h0 >= 1.0f) ? 0.0f : h0;
    v.y = (h1 >= 1.0f) ? 0.0f : h1;
    v.z = (h2 >= 1.0f) ? 0.0f : h2;
    v.w = (h3 >= 1.0f) ? 0.0f : h3;
    return s;
}

#define BLOCK 128

// T must be a multiple of 4 (T=32 here).
__global__ __launch_bounds__(BLOCK, 10) void if_scan_final(
    const float4* __restrict__ x,   // [T, n4]
    const float4* __restrict__ v0,  // [n4]
    float4* __restrict__ out,       // [T, n4]
    int n4, int T)
{
    int i = blockIdx.x * BLOCK + threadIdx.x;
    if (i >= n4) return;

    uint64_t pl = policy_ld();
    uint64_t ps = policy_st();

    float4 v = v0[i];
    const float4* xp = x + i;
    float4* op = out + i;

    long long stride = n4;

    // prologue: load batch 0
    float4 buf[4];
    #pragma unroll
    for (int k = 0; k < 4; ++k)
        buf[k] = ldg_h(xp + (long long)k * stride, pl);
    xp += 4 * stride;

    for (int t = 4; t < T; t += 4) {
        // prefetch next batch (8 loads in flight per thread)
        float4 nxt[4];
        #pragma unroll
        for (int k = 0; k < 4; ++k)
            nxt[k] = ldg_h(xp + (long long)k * stride, pl);
        xp += 4 * stride;

        // compute + store current batch (write burst)
        #pragma unroll
        for (int k = 0; k < 4; ++k) {
            float4 s = if_step(buf[k], v);
            stg_h(op, s, ps);
            op += stride;
        }

        #pragma unroll
        for (int k = 0; k < 4; ++k) buf[k] = nxt[k];
    }

    // epilogue
    #pragma unroll
    for (int k = 0; k < 4; ++k) {
        float4 s = if_step(buf[k], v);
        stg_h(op, s, ps);
        op += stride;
    }
}

// Generic fallback for T not divisible by 4 (not hit for this shape).
__global__ __launch_bounds__(BLOCK) void if_scan_plain(
    const float4* __restrict__ x,
    const float4* __restrict__ v0,
    float4* __restrict__ out,
    int n4, int T)
{
    int i = blockIdx.x * BLOCK + threadIdx.x;
    if (i >= n4) return;

    float4 v = v0[i];
    const float4* xp = x + i;
    float4* op = out + i;

    for (int t = 0; t < T; ++t) {
        float4 xv = __ldcs(xp); xp += n4;
        float4 s = if_step(xv, v);
        __stcs(op, s); op += n4;
    }
}

extern "C" void kernel_launch(void* const* d_in, const int* in_sizes, int n_in,
                              void* d_out, int out_size)
{
    const float* x_seq  = (const float*)d_in[0];   // [T, B, D]
    const float* v_init = (const float*)d_in[1];   // [B, D]

    int N = in_sizes[1];              // B * D
    int T = in_sizes[0] / N;          // timesteps
    int n4 = N / 4;

    int grid = (n4 + BLOCK - 1) / BLOCK;

    if ((T & 3) == 0) {
        if_scan_final<<<grid, BLOCK>>>(
            (const float4*)x_seq, (const float4*)v_init,
            (float4*)d_out, n4, T);
    } else {
        if_scan_plain<<<grid, BLOCK>>>(
            (const float4*)x_seq, (const float4*)v_init,
            (float4*)d_out, n4, T);
    }
}

// round 14
// speedup vs baseline: 1.0101x; 1.0014x over previous
#include <cuda_runtime.h>
#include <cstdint>

// IF neuron multi-step scan, hard reset:
//   h_t = x_t + v_{t-1};  s_t = (h_t >= 1) ? 1 : 0;  v_t = s_t ? 0 : h_t
//
// FINAL (locked): block=128, one float4 lane per thread, batch-4
// double-buffered prefetch (8 LDG.128 in flight per thread).
//   - loads:  L2::evict_first (zero-reuse stream)
//   - stores: fractional L2::evict_last 0.8 / evict_first secondary
//     (pins ~107MB of the 134MB output in the 126MB L2)
//
// Floor analysis (confirmed over R11-R13): 268MB compulsory L2 traffic at
// the ~6300B/cyc path-independent LTS cap ≈ 37us; measured 36.9-37.2us =
// 7.2+TB/s through LTS. Bytes are irreducible (no reuse, fp32 output,
// writes traverse LTS even when absorbed in L2). All scheduling variants
// (MLP 4-8, occ 40-77%, 128/256-bit, cp.async pipelines) converged here.

__device__ __forceinline__ uint64_t policy_st()
{
    uint64_t p;
    asm("createpolicy.fractional.L2::evict_last.L2::evict_first.b64 %0, 0.8;"
        : "=l"(p));
    return p;
}

__device__ __forceinline__ uint64_t policy_ld()
{
    uint64_t p;
    asm("createpolicy.fractional.L2::evict_first.b64 %0, 1.0;" : "=l"(p));
    return p;
}

__device__ __forceinline__ float4 ldg_h(const float4* p, uint64_t pol)
{
    float4 r;
    asm("ld.global.nc.L2::cache_hint.v4.f32 {%0,%1,%2,%3}, [%4], %5;"
        : "=f"(r.x), "=f"(r.y), "=f"(r.z), "=f"(r.w)
        : "l"(p), "l"(pol));
    return r;
}

__device__ __forceinline__ void stg_h(float4* p, float4 v, uint64_t pol)
{
    asm volatile("st.global.L2::cache_hint.v4.f32 [%0], {%1,%2,%3,%4}, %5;"
                 :: "l"(p), "f"(v.x), "f"(v.y), "f"(v.z), "f"(v.w), "l"(pol)
                 : "memory");
}

__device__ __forceinline__ float4 if_step(float4 xv, float4& v)
{
    float h0 = xv.x + v.x;
    float h1 = xv.y + v.y;
    float h2 = xv.z + v.z;
    float h3 = xv.w + v.w;

    float4 s;
    s.x = (h0 >= 1.0f) ? 1.0f : 0.0f;
    s.y = (h1 >= 1.0f) ? 1.0f : 0.0f;
    s.z = (h2 >= 1.0f) ? 1.0f : 0.0f;
    s.w = (h3 >= 1.0f) ? 1.0f : 0.0f;

    v.x = (h0 >= 1.0f) ? 0.0f : h0;
    v.y = (h1 >= 1.0f) ? 0.0f : h1;
    v.z = (h2 >= 1.0f) ? 0.0f : h2;
    v.w = (h3 >= 1.0f) ? 0.0f : h3;
    return s;
}

#define BLOCK 128

// T must be a multiple of 4 (T=32 here).
__global__ __launch_bounds__(BLOCK, 10) void if_scan_final(
    const float4* __restrict__ x,   // [T, n4]
    const float4* __restrict__ v0,  // [n4]
    float4* __restrict__ out,       // [T, n4]
    int n4, int T)
{
    int i = blockIdx.x * BLOCK + threadIdx.x;
    if (i >= n4) return;

    uint64_t pl = policy_ld();
    uint64_t ps = policy_st();

    float4 v = v0[i];
    const float4* xp = x + i;
    float4* op = out + i;

    long long stride = n4;

    // prologue: load batch 0
    float4 buf[4];
    #pragma unroll
    for (int k = 0; k < 4; ++k)
        buf[k] = ldg_h(xp + (long long)k * stride, pl);
    xp += 4 * stride;

    for (int t = 4; t < T; t += 4) {
        // prefetch next batch (8 loads in flight per thread)
        float4 nxt[4];
        #pragma unroll
        for (int k = 0; k < 4; ++k)
            nxt[k] = ldg_h(xp + (long long)k * stride, pl);
        xp += 4 * stride;

        // compute + store current batch (write burst)
        #pragma unroll
        for (int k = 0; k < 4; ++k) {
            float4 s = if_step(buf[k], v);
            stg_h(op, s, ps);
            op += stride;
        }

        #pragma unroll
        for (int k = 0; k < 4; ++k) buf[k] = nxt[k];
    }

    // epilogue
    #pragma unroll
    for (int k = 0; k < 4; ++k) {
        float4 s = if_step(buf[k], v);
        stg_h(op, s, ps);
        op += stride;
    }
}

// Generic fallback for T not divisible by 4 (not hit for this shape).
__global__ __launch_bounds__(BLOCK) void if_scan_plain(
    const float4* __restrict__ x,
    const float4* __restrict__ v0,
    float4* __restrict__ out,
    int n4, int T)
{
    int i = blockIdx.x * BLOCK + threadIdx.x;
    if (i >= n4) return;

    float4 v = v0[i];
    const float4* xp = x + i;
    float4* op = out + i;

    for (int t = 0; t < T; ++t) {
        float4 xv = __ldcs(xp); xp += n4;
        float4 s = if_step(xv, v);
        __stcs(op, s); op += n4;
    }
}

extern "C" void kernel_launch(void* const* d_in, const int* in_sizes, int n_in,
                              void* d_out, int out_size)
{
    const float* x_seq  = (const float*)d_in[0];   // [T, B, D]
    const float* v_init = (const float*)d_in[1];   // [B, D]

    int N = in_sizes[1];              // B * D
    int T = in_sizes[0] / N;          // timesteps
    int n4 = N / 4;

    int grid = (n4 + BLOCK - 1) / BLOCK;

    if ((T & 3) == 0) {
        if_scan_final<<<grid, BLOCK>>>(
            (const float4*)x_seq, (const float4*)v_init,
            (float4*)d_out, n4, T);
    } else {
        if_scan_plain<<<grid, BLOCK>>>(
            (const float4*)x_seq, (const float4*)v_init,
            (float4*)d_out, n4, T);
    }
}

// round 15
// speedup vs baseline: 1.0499x; 1.0393x over previous
#include <cuda_runtime.h>

// IF neuron multi-step scan, hard reset:
//   h_t = x_t + v_{t-1};  s_t = (h_t >= 1) ? 1 : 0;  v_t = s_t ? 0 : h_t
//
// FINAL = R10 (best measured WALL time, 45.6us): block=128, one float4 lane
// per thread, batch-4 double-buffered prefetch (8 LDG.128 in flight),
// plain __ldcs/__stcs.
//
// Why not the createpolicy variants (R11-R14): their ncu kernel dur was
// ~1us better (36.9-37.4 vs 38.0) but ncu measures with --cache-control all
// (flushed caches); under the harness's steady-state graph replay their
// WALL time was consistently ~1.8us WORSE (47.3-47.8 vs 45.6-45.8, n=4 vs
// n=2, tight variance). Wall is ground truth; policies are a cold-cache
// measurement artifact here.
//
// Floor analysis: 268MB compulsory L2 traffic at the ~path-independent LTS
// cap ≈ 37-38us kernel. All scheduling variants (MLP 4-8, occ 40-77%,
// 128/256-bit, cp.async pipelines) converged to this; bytes are irreducible
// (zero reuse, fp32 output, writes traverse LTS even when L2-absorbed).

__device__ __forceinline__ float4 if_step(float4 xv, float4& v)
{
    float h0 = xv.x + v.x;
    float h1 = xv.y + v.y;
    float h2 = xv.z + v.z;
    float h3 = xv.w + v.w;

    float4 s;
    s.x = (h0 >= 1.0f) ? 1.0f : 0.0f;
    s.y = (h1 >= 1.0f) ? 1.0f : 0.0f;
    s.z = (h2 >= 1.0f) ? 1.0f : 0.0f;
    s.w = (h3 >= 1.0f) ? 1.0f : 0.0f;

    v.x = (h0 >= 1.0f) ? 0.0f : h0;
    v.y = (h1 >= 1.0f) ? 0.0f : h1;
    v.z = (h2 >= 1.0f) ? 0.0f : h2;
    v.w = (h3 >= 1.0f) ? 0.0f : h3;
    return s;
}

#define BLOCK 128

// T must be a multiple of 4 (T=32 here).
__global__ __launch_bounds__(BLOCK, 10) void if_scan_b4_128(
    const float4* __restrict__ x,   // [T, n4]
    const float4* __restrict__ v0,  // [n4]
    float4* __restrict__ out,       // [T, n4]
    int n4, int T)
{
    int i = blockIdx.x * BLOCK + threadIdx.x;
    if (i >= n4) return;

    float4 v = v0[i];
    const float4* xp = x + i;
    float4* op = out + i;

    long long stride = n4;

    // prologue: load batch 0
    float4 buf[4];
    #pragma unroll
    for (int k = 0; k < 4; ++k)
        buf[k] = __ldcs(xp + (long long)k * stride);
    xp += 4 * stride;

    for (int t = 4; t < T; t += 4) {
        // prefetch next batch (8 loads in flight per thread)
        float4 nxt[4];
        #pragma unroll
        for (int k = 0; k < 4; ++k)
            nxt[k] = __ldcs(xp + (long long)k * stride);
        xp += 4 * stride;

        // compute + store current batch (write burst)
        #pragma unroll
        for (int k = 0; k < 4; ++k) {
            float4 s = if_step(buf[k], v);
            __stcs(op, s);
            op += stride;
        }

        #pragma unroll
        for (int k = 0; k < 4; ++k) buf[k] = nxt[k];
    }

    // epilogue
    #pragma unroll
    for (int k = 0; k < 4; ++k) {
        float4 s = if_step(buf[k], v);
        __stcs(op, s);
        op += stride;
    }
}

// Generic fallback for T not divisible by 4 (not hit for this shape).
__global__ __launch_bounds__(BLOCK) void if_scan_plain(
    const float4* __restrict__ x,
    const float4* __restrict__ v0,
    float4* __restrict__ out,
    int n4, int T)
{
    int i = blockIdx.x * BLOCK + threadIdx.x;
    if (i >= n4) return;

    float4 v = v0[i];
    const float4* xp = x + i;
    float4* op = out + i;

    for (int t = 0; t < T; ++t) {
        float4 xv = __ldcs(xp); xp += n4;
        float4 s = if_step(xv, v);
        __stcs(op, s); op += n4;
    }
}

extern "C" void kernel_launch(void* const* d_in, const int* in_sizes, int n_in,
                              void* d_out, int out_size)
{
    const float* x_seq  = (const float*)d_in[0];   // [T, B, D]
    const float* v_init = (const float*)d_in[1];   // [B, D]

    int N = in_sizes[1];              // B * D
    int T = in_sizes[0] / N;          // timesteps
    int n4 = N / 4;

    int grid = (n4 + BLOCK - 1) / BLOCK;

    if ((T & 3) == 0) {
        if_scan_b4_128<<<grid, BLOCK>>>(
            (const float4*)x_seq, (const float4*)v_init,
            (float4*)d_out, n4, T);
    } else {
        if_scan_plain<<<grid, BLOCK>>>(
            (const float4*)x_seq, (const float4*)v_init,
            (float4*)d_out, n4, T);
    }
}